// round 3
// baseline (speedup 1.0000x reference)
#include <cuda_runtime.h>
#include <cuda_bf16.h>
#include <cstdint>

// ---------------------------------------------------------------------------
// ChannelMultiHeadAttention: B=1024, C=64, SEQ=14, EMB=64, fp32.
//   energy = x A x^T + (x u1) 1^T + 1 (x u2)^T + c0,  A=Wq^T Wk
//   out    = (att @ x) Wv^T + bv
// R3: wavefront-minimized smem access patterns; f32x2 throughout.
// ---------------------------------------------------------------------------

#define ULL unsigned long long
#define FULLMASK 0xffffffffu

__device__ float4 g_Yw[1024];   // [d2*32+cp] = (A[2d2][2cp],A[2d2][2cp+1],A[2d2+1][2cp],A[2d2+1][2cp+1])
__device__ float4 g_Ww[1024];   // same layout for B=Wv^T: B[d][e]=Wv[e][d]
__device__ float  g_u1[64], g_u2[64], g_c0[1];

__device__ __forceinline__ ULL fma2(ULL a, ULL b, ULL c) {
    ULL d; asm("fma.rn.f32x2 %0, %1, %2, %3;" : "=l"(d) : "l"(a), "l"(b), "l"(c)); return d;
}
__device__ __forceinline__ ULL add2(ULL a, ULL b) {
    ULL d; asm("add.rn.f32x2 %0, %1, %2;" : "=l"(d) : "l"(a), "l"(b)); return d;
}
__device__ __forceinline__ float hsum2(ULL u) {
    float lo, hi; asm("mov.b64 {%0,%1}, %2;" : "=f"(lo), "=f"(hi) : "l"(u)); return lo + hi;
}
__device__ __forceinline__ ULL dup2(float v) {
    ULL u; asm("mov.b64 %0, {%1,%1};" : "=l"(u) : "f"(v)); return u;
}
__device__ __forceinline__ float2 unp2(ULL u) {
    float2 f; asm("mov.b64 {%0,%1}, %2;" : "=f"(f.x), "=f"(f.y) : "l"(u)); return f;
}

// ---------------------------------------------------------------------------
__global__ void prep_kernel(const float* __restrict__ Wq, const float* __restrict__ bq,
                            const float* __restrict__ Wk, const float* __restrict__ bk,
                            const float* __restrict__ Wv) {
    __shared__ float sWq[4096], sWk[4096], sA[4096];
    int t = threadIdx.x;
    for (int i = t; i < 4096; i += 256) { sWq[i] = Wq[i]; sWk[i] = Wk[i]; }
    __syncthreads();
    for (int idx = t; idx < 4096; idx += 256) {
        int d = idx >> 6, e = idx & 63;
        float a = 0.f;
        #pragma unroll 8
        for (int f = 0; f < 64; f++) a += sWq[f * 64 + d] * sWk[f * 64 + e];
        sA[idx] = a;
    }
    __syncthreads();
    for (int idx = t; idx < 1024; idx += 256) {
        int d2 = idx >> 5, cp = idx & 31;
        g_Yw[idx] = make_float4(sA[(2 * d2) * 64 + 2 * cp],     sA[(2 * d2) * 64 + 2 * cp + 1],
                                sA[(2 * d2 + 1) * 64 + 2 * cp], sA[(2 * d2 + 1) * 64 + 2 * cp + 1]);
        g_Ww[idx] = make_float4(Wv[(2 * cp) * 64 + 2 * d2],     Wv[(2 * cp + 1) * 64 + 2 * d2],
                                Wv[(2 * cp) * 64 + 2 * d2 + 1], Wv[(2 * cp + 1) * 64 + 2 * d2 + 1]);
    }
    if (t < 64) {
        float s1 = 0.f, s2 = 0.f;
        for (int f = 0; f < 64; f++) {
            s1 += sWq[f * 64 + t] * bk[f];
            s2 += sWk[f * 64 + t] * bq[f];
        }
        g_u1[t] = s1; g_u2[t] = s2;
    }
    if (t == 0) {
        float c = 0.f;
        for (int f = 0; f < 64; f++) c += bq[f] * bk[f];
        g_c0[0] = c;
    }
}

// ---------------------------------------------------------------------------
// Main kernel: 1 warp = 1 pair, 8 pairs/CTA.
// x/y tiles: 16 rows x 34 ULL; floats 0..31 at ULL[0..16), 32..63 at ULL[18..34).
// ---------------------------------------------------------------------------
static const int XR = 34;
static const int TILE = 16 * XR;     // 544
static const int SMEM_BYTES = 12800 * 8 + 2480 * 4;   // 112320 B

__global__ __launch_bounds__(256, 2)
void attn_kernel(const float* __restrict__ x, const float* __restrict__ wc,
                 const float* __restrict__ lng, const float* __restrict__ lnb,
                 const float* __restrict__ bv, float* __restrict__ out) {
    extern __shared__ ULL sm[];
    ULL* sYw = sm;                 // 2048
    ULL* sWw = sm + 2048;          // 2048
    ULL* sx  = sm + 4096;          // 8*544
    ULL* sy  = sx + 8 * TILE;      // 8*544
    float* fb   = (float*)(sm + 12800);
    float* sep  = fb;              // 8*224 (stride 16)
    float* swcs = fb + 1792;       // 196
    float* su1  = fb + 1988;       // 72 (padded halves)
    float* su2  = fb + 2060;       // 72
    float* sbv  = fb + 2132;       // 64
    float* slg  = fb + 2196;       // 14
    float* slb  = fb + 2210;       // 14
    float* sxu1 = fb + 2224;       // 8*16
    float* sxu2 = fb + 2352;       // 8*16

    const int t = threadIdx.x, wid = t >> 5, l = t & 31;

    // stage constants
    const ULL* gy = (const ULL*)g_Yw;
    const ULL* gw = (const ULL*)g_Ww;
    for (int i = t; i < 2048; i += 256) { sYw[i] = gy[i]; sWw[i] = gw[i]; }
    if (t < 64) {
        int s = t + ((t >= 32) ? 4 : 0);
        su1[s] = g_u1[t]; su2[s] = g_u2[t]; sbv[t] = bv[t];
    }
    for (int i = t; i < 196; i += 256) swcs[i] = wc[i];
    if (t < 14) { slg[t] = lng[t]; slb[t] = lnb[t]; }
    __syncthreads();
    const float c0 = g_c0[0];

    const size_t pair = (size_t)blockIdx.x * 8 + wid;
    const float* xg = x + pair * 896;
    ULL* xw = sx + wid * TILE;
    ULL* yw = sy + wid * TILE;
    float* sepp = sep + wid * 224;
    float* sx1 = sxu1 + wid * 16;
    float* sx2 = sxu2 + wid * 16;

    // zero padding rows 14,15
    for (int k = l; k < 68; k += 32) xw[14 * XR + k] = 0ULL;
    // load x tile
    const ulonglong2* xg2 = (const ulonglong2*)xg;
    #pragma unroll
    for (int k = l, it = 0; it < 7; k += 32, it++) {
        ulonglong2 v = xg2[k];
        int row = k >> 4, c4 = k & 15;
        int slot = 2 * c4 + ((c4 >= 8) ? 2 : 0);
        *(ulonglong2*)&xw[row * XR + slot] = v;
    }
    __syncwarp();

    const int g = l & 7, r = l >> 3, i14 = l & 15, h = l >> 4;

    // ---- xu pass: xu1[i]=x_i.u1, xu2[i]=x_i.u2 (28 lanes, half-split) ----
    {
        const ULL* xp  = xw + i14 * XR + h * 18;
        const ULL* u1p = (const ULL*)su1 + h * 18;
        const ULL* u2p = (const ULL*)su2 + h * 18;
        ULL s1 = 0, s2 = 0;
        #pragma unroll
        for (int c = 0; c < 8; c++) {
            ulonglong2 xv  = *(const ulonglong2*)&xp[2 * c];
            ulonglong2 u1v = *(const ulonglong2*)&u1p[2 * c];
            ulonglong2 u2v = *(const ulonglong2*)&u2p[2 * c];
            s1 = fma2(xv.x, u1v.x, s1); s1 = fma2(xv.y, u1v.y, s1);
            s2 = fma2(xv.x, u2v.x, s2); s2 = fma2(xv.y, u2v.y, s2);
        }
        float a1 = hsum2(s1), a2 = hsum2(s2);
        a1 += __shfl_xor_sync(FULLMASK, a1, 16);
        a2 += __shfl_xor_sync(FULLMASK, a2, 16);
        if (h == 0) { sx1[i14] = a1; sx2[i14] = a2; }
    }

    // ---- Y: y = x @ A  (lane: colgroup g -> cp=g+8m, rowgroup r -> rows r+4k) ----
    {
        ULL acc[4][4];
        #pragma unroll
        for (int k = 0; k < 4; k++)
            #pragma unroll
            for (int m = 0; m < 4; m++) acc[k][m] = 0ULL;

        #pragma unroll 4
        for (int d4 = 0; d4 < 16; d4++) {
            const int c4 = d4 + (d4 >> 3);
            ULL a[4][4];
            #pragma unroll
            for (int m = 0; m < 4; m++) {
                ulonglong2 v0 = *(const ulonglong2*)&sYw[((2 * d4) * 32 + g + 8 * m) * 2];
                ulonglong2 v1 = *(const ulonglong2*)&sYw[((2 * d4 + 1) * 32 + g + 8 * m) * 2];
                a[m][0] = v0.x; a[m][1] = v0.y; a[m][2] = v1.x; a[m][3] = v1.y;
            }
            #pragma unroll
            for (int k = 0; k < 4; k++) {
                int row = r + 4 * k;
                float4 xv = *(const float4*)((const float*)(xw + row * XR) + 4 * c4);
                ULL x0 = dup2(xv.x), x1 = dup2(xv.y), x2 = dup2(xv.z), x3 = dup2(xv.w);
                #pragma unroll
                for (int m = 0; m < 4; m++) {
                    acc[k][m] = fma2(x0, a[m][0], acc[k][m]);
                    acc[k][m] = fma2(x1, a[m][1], acc[k][m]);
                    acc[k][m] = fma2(x2, a[m][2], acc[k][m]);
                    acc[k][m] = fma2(x3, a[m][3], acc[k][m]);
                }
            }
        }
        #pragma unroll
        for (int k = 0; k < 4; k++) {
            int row = r + 4 * k;
            #pragma unroll
            for (int m = 0; m < 4; m++) {
                int cp = g + 8 * m;
                int slot = cp + ((cp >= 16) ? 2 : 0);
                yw[row * XR + slot] = acc[k][m];
            }
        }
    }
    __syncwarp();

    // ---- energy[i][j] = y_i . x_j (+bias terms), 28 lanes (i, d-half) ----
    {
        ULL yc[16];
        const ULL* yp = yw + i14 * XR + h * 18;
        #pragma unroll
        for (int c = 0; c < 8; c++) {
            ulonglong2 v = *(const ulonglong2*)&yp[2 * c];
            yc[2 * c] = v.x; yc[2 * c + 1] = v.y;
        }
        float ep[14];
        #pragma unroll
        for (int j = 0; j < 14; j++) {
            const ULL* xp = xw + j * XR + h * 18;
            ULL s0 = 0, s1 = 0;
            #pragma unroll
            for (int c = 0; c < 8; c++) {
                ulonglong2 v = *(const ulonglong2*)&xp[2 * c];
                s0 = fma2(yc[2 * c], v.x, s0);
                s1 = fma2(yc[2 * c + 1], v.y, s1);
            }
            ep[j] = hsum2(s0) + hsum2(s1);
        }
        #pragma unroll
        for (int j = 0; j < 14; j++) ep[j] += __shfl_xor_sync(FULLMASK, ep[j], 16);
        if (h == 0 && i14 < 14) {
            float b = sx1[i14] + c0;
            #pragma unroll
            for (int j = 0; j < 14; j++) sepp[i14 * 16 + j] = ep[j] + b + sx2[j];
        }
    }
    __syncwarp();

    // ---- mix (w_c @ energy) + LayerNorm + softmax (lanes 0..13) ----
    float att[14];
    #pragma unroll
    for (int v = 0; v < 14; v++) att[v] = 0.f;
    if (l < 14) {
        ULL e1[7];
        #pragma unroll
        for (int c = 0; c < 7; c++) e1[c] = 0ULL;
        #pragma unroll
        for (int li = 0; li < 14; li++) {
            ULL wp = dup2(swcs[l * 14 + li]);
            const float* sr = sepp + li * 16;
            float4 q0 = *(const float4*)sr;
            float4 q1 = *(const float4*)(sr + 4);
            float4 q2 = *(const float4*)(sr + 8);
            ULL lv = *(const ULL*)(sr + 12);
            e1[0] = fma2(wp, ((const ULL*)&q0)[0], e1[0]);
            e1[1] = fma2(wp, ((const ULL*)&q0)[1], e1[1]);
            e1[2] = fma2(wp, ((const ULL*)&q1)[0], e1[2]);
            e1[3] = fma2(wp, ((const ULL*)&q1)[1], e1[3]);
            e1[4] = fma2(wp, ((const ULL*)&q2)[0], e1[4]);
            e1[5] = fma2(wp, ((const ULL*)&q2)[1], e1[5]);
            e1[6] = fma2(wp, lv, e1[6]);
        }
        float e[14];
        #pragma unroll
        for (int c = 0; c < 7; c++) { float2 f = unp2(e1[c]); e[2 * c] = f.x; e[2 * c + 1] = f.y; }
        float mu = 0.f;
        #pragma unroll
        for (int v = 0; v < 14; v++) mu += e[v];
        mu *= (1.0f / 14.0f);
        float var = 0.f;
        #pragma unroll
        for (int v = 0; v < 14; v++) { float d = e[v] - mu; var += d * d; }
        var *= (1.0f / 14.0f);
        float rs = rsqrtf(var + 1e-5f);
        float mx = -1e30f;
        #pragma unroll
        for (int v = 0; v < 14; v++) {
            float tv = ((e[v] - mu) * rs * slg[v] + slb[v]) * 0.125f;
            e[v] = tv;
            mx = fmaxf(mx, tv);
        }
        float s = 0.f;
        #pragma unroll
        for (int v = 0; v < 14; v++) { float ev = __expf(e[v] - mx); att[v] = ev; s += ev; }
        float inv = 1.0f / s;
        #pragma unroll
        for (int v = 0; v < 14; v++) att[v] *= inv;
    }

    // ---- z = att @ x  (28 lanes: row i14, d-half h), overwrite y tile ----
    {
        ULL ap[14];
        #pragma unroll
        for (int j = 0; j < 14; j++) {
            float av = __shfl_sync(FULLMASK, att[j], i14);
            ap[j] = dup2(av);
        }
        ULL zc[16];
        #pragma unroll
        for (int c = 0; c < 16; c++) zc[c] = 0ULL;
        #pragma unroll
        for (int j = 0; j < 14; j++) {
            const ULL* xp = xw + j * XR + h * 18;
            #pragma unroll
            for (int c = 0; c < 8; c++) {
                ulonglong2 v = *(const ulonglong2*)&xp[2 * c];
                zc[2 * c]     = fma2(ap[j], v.x, zc[2 * c]);
                zc[2 * c + 1] = fma2(ap[j], v.y, zc[2 * c + 1]);
            }
        }
        if (i14 < 14) {
            ULL* zp = yw + i14 * XR + h * 18;
            #pragma unroll
            for (int c = 0; c < 8; c++)
                *(ulonglong2*)&zp[2 * c] = make_ulonglong2(zc[2 * c], zc[2 * c + 1]);
        }
    }
    __syncwarp();

    // ---- out = z @ Wv^T + bv ----
    {
        ULL acc[4][4];
        #pragma unroll
        for (int k = 0; k < 4; k++)
            #pragma unroll
            for (int m = 0; m < 4; m++) acc[k][m] = 0ULL;

        #pragma unroll 4
        for (int d4 = 0; d4 < 16; d4++) {
            const int c4 = d4 + (d4 >> 3);
            ULL a[4][4];
            #pragma unroll
            for (int m = 0; m < 4; m++) {
                ulonglong2 v0 = *(const ulonglong2*)&sWw[((2 * d4) * 32 + g + 8 * m) * 2];
                ulonglong2 v1 = *(const ulonglong2*)&sWw[((2 * d4 + 1) * 32 + g + 8 * m) * 2];
                a[m][0] = v0.x; a[m][1] = v0.y; a[m][2] = v1.x; a[m][3] = v1.y;
            }
            #pragma unroll
            for (int k = 0; k < 4; k++) {
                int row = r + 4 * k;
                float4 zv = *(const float4*)((const float*)(yw + row * XR) + 4 * c4);
                ULL z0 = dup2(zv.x), z1 = dup2(zv.y), z2 = dup2(zv.z), z3 = dup2(zv.w);
                #pragma unroll
                for (int m = 0; m < 4; m++) {
                    acc[k][m] = fma2(z0, a[m][0], acc[k][m]);
                    acc[k][m] = fma2(z1, a[m][1], acc[k][m]);
                    acc[k][m] = fma2(z2, a[m][2], acc[k][m]);
                    acc[k][m] = fma2(z3, a[m][3], acc[k][m]);
                }
            }
        }
        float* og = out + pair * 896;
        #pragma unroll
        for (int m = 0; m < 4; m++) {
            int cp = g + 8 * m;
            ULL bvv = *(const ULL*)&sbv[2 * cp];
            #pragma unroll
            for (int k = 0; k < 4; k++) {
                int row = r + 4 * k;
                if (row < 14) {
                    *(ULL*)&og[row * 64 + 2 * cp] = add2(acc[k][m], bvv);
                }
            }
        }
    }
}

// ---------------------------------------------------------------------------
extern "C" void kernel_launch(void* const* d_in, const int* in_sizes, int n_in,
                              void* d_out, int out_size) {
    const float* x   = (const float*)d_in[0];
    const float* wc  = (const float*)d_in[1];
    const float* Wq  = (const float*)d_in[2];
    const float* bq  = (const float*)d_in[3];
    const float* Wk  = (const float*)d_in[4];
    const float* bk  = (const float*)d_in[5];
    const float* Wv  = (const float*)d_in[6];
    const float* bv  = (const float*)d_in[7];
    const float* lng = (const float*)d_in[8];
    const float* lnb = (const float*)d_in[9];
    float* out = (float*)d_out;

    cudaFuncSetAttribute(attn_kernel, cudaFuncAttributeMaxDynamicSharedMemorySize, SMEM_BYTES);

    prep_kernel<<<1, 256>>>(Wq, bq, Wk, bk, Wv);
    attn_kernel<<<8192, 256, SMEM_BYTES>>>(x, wc, lng, lnb, bv, out);
}

// round 4
// speedup vs baseline: 1.5744x; 1.5744x over previous
#include <cuda_runtime.h>
#include <cstdint>

// ---------------------------------------------------------------------------
// ChannelMultiHeadAttention, fp32 in/out, tf32 tensor-core compute.
//   energy = x A x^T + xu1 1^T + 1 xu2^T + c0,  A = Wq^T Wk
//   out    = (att @ x) Wv^T + bv
// R4: per-warp mma.sync.m16n8k8.tf32 for all 5 GEMM phases.
// ---------------------------------------------------------------------------

#define FULLMASK 0xffffffffu

__device__ float g_A[4096];    // A[d][e] = (Wq^T Wk)[d][e], tf32-rounded
__device__ float g_W[4096];    // W[d][e] = Wv[e][d], tf32-rounded
__device__ float g_wc[256];    // w_c padded 16x16, tf32-rounded (pad = 0)
__device__ float g_u1[64], g_u2[64], g_c0[1];

__device__ __forceinline__ uint32_t tf32r(float f) {
    uint32_t u; asm("cvt.rna.tf32.f32 %0, %1;" : "=r"(u) : "f"(f)); return u;
}
__device__ __forceinline__ float tf32f(float f) { return __uint_as_float(tf32r(f)); }
__device__ __forceinline__ uint32_t fbits(float f) { return __float_as_uint(f); }

__device__ __forceinline__ void mma8(float* d, uint32_t a0, uint32_t a1, uint32_t a2,
                                     uint32_t a3, uint32_t b0, uint32_t b1) {
    asm("mma.sync.aligned.m16n8k8.row.col.f32.tf32.tf32.f32 "
        "{%0,%1,%2,%3}, {%4,%5,%6,%7}, {%8,%9}, {%0,%1,%2,%3};"
        : "+f"(d[0]), "+f"(d[1]), "+f"(d[2]), "+f"(d[3])
        : "r"(a0), "r"(a1), "r"(a2), "r"(a3), "r"(b0), "r"(b1));
}

// ---------------------------------------------------------------------------
__global__ void prep_kernel(const float* __restrict__ Wq, const float* __restrict__ bq,
                            const float* __restrict__ Wk, const float* __restrict__ bk,
                            const float* __restrict__ Wv, const float* __restrict__ wc) {
    __shared__ float sWq[4096], sWk[4096];
    int t = threadIdx.x;
    for (int i = t; i < 4096; i += 256) { sWq[i] = Wq[i]; sWk[i] = Wk[i]; }
    __syncthreads();
    for (int idx = t; idx < 4096; idx += 256) {
        int d = idx >> 6, e = idx & 63;
        float a = 0.f;
        #pragma unroll 8
        for (int f = 0; f < 64; f++) a += sWq[f * 64 + d] * sWk[f * 64 + e];
        g_A[idx] = tf32f(a);
        g_W[idx] = tf32f(Wv[e * 64 + d]);   // W[d][e] = Wv[e][d]
    }
    if (t < 256) {
        int a = t >> 4, c = t & 15;
        float v = (a < 14 && c < 14) ? wc[a * 14 + c] : 0.f;
        g_wc[t] = tf32f(v);
    }
    if (t < 64) {
        float s1 = 0.f, s2 = 0.f;
        for (int f = 0; f < 64; f++) {
            s1 += sWq[f * 64 + t] * bk[f];
            s2 += sWk[f * 64 + t] * bq[f];
        }
        g_u1[t] = s1; g_u2[t] = s2;
    }
    if (t == 0) {
        float c = 0.f;
        for (int f = 0; f < 64; f++) c += bq[f] * bk[f];
        g_c0[0] = c;
    }
}

// ---------------------------------------------------------------------------
// Main: 1 warp = 1 pair, 8 warps/CTA, 8192 CTAs.
// Smem strides: x/y tiles 68 (A-frag clean), sA/sW 72 (B-frag clean),
// energy/att 24 (B-frag clean), w_c 20 (A-frag clean).
// ---------------------------------------------------------------------------
static const int SMEM_FLOATS = 27424;   // 109696 bytes

__global__ __launch_bounds__(256, 2)
void attn_kernel(const float* __restrict__ x, const float* __restrict__ bv,
                 const float* __restrict__ lng, const float* __restrict__ lnb,
                 float* __restrict__ out) {
    extern __shared__ float sf[];
    float* sA  = sf;            // 64 x 72
    float* sW  = sf + 4608;     // 64 x 72
    float* swc = sf + 9216;     // 16 x 20
    float* su1 = sf + 9536;
    float* su2 = sf + 9600;
    float* sbv = sf + 9664;
    float* slg = sf + 9728;
    float* slb = sf + 9744;     // tiles start at 9760

    const int t = threadIdx.x, w = t >> 5, l = t & 31;
    const int g = l >> 2, tg = l & 3;

    for (int i = t; i < 4096; i += 256) {
        int d = i >> 6, e = i & 63;
        sA[d * 72 + e] = g_A[i];
        sW[d * 72 + e] = g_W[i];
    }
    { int a = t >> 4, c = t & 15; swc[a * 20 + c] = g_wc[t]; }
    if (t < 64) { su1[t] = g_u1[t]; su2[t] = g_u2[t]; sbv[t] = bv[t]; }
    if (t < 16) {
        slg[t] = (t < 14) ? lng[t] : 0.f;
        slb[t] = (t < 14) ? lnb[t] : 0.f;
    }
    __syncthreads();
    const float c0 = g_c0[0];

    float* sx   = sf + 9760 + w * 2208;   // 16 x 68
    float* sy   = sx + 1088;              // 16 x 68 (y -> energy -> att -> z)
    float* sxu1 = sx + 2176;              // 16
    float* sxu2 = sx + 2192;              // 16

    const size_t pair = (size_t)blockIdx.x * 8 + w;

    // ---- load x tile, round to tf32, zero pad rows 14/15 ----
    const float4* xg4 = (const float4*)(x + pair * 896);
    #pragma unroll
    for (int it = 0; it < 7; it++) {
        int k = l + 32 * it;
        float4 v = xg4[k];
        int row = k >> 4, c = (k & 15) << 2;
        *(float4*)(sx + row * 68 + c) =
            make_float4(tf32f(v.x), tf32f(v.y), tf32f(v.z), tf32f(v.w));
    }
    if (l < 16) {
        float4 z4 = make_float4(0.f, 0.f, 0.f, 0.f);
        *(float4*)(sx + 14 * 68 + 4 * l) = z4;
        *(float4*)(sx + 15 * 68 + 4 * l) = z4;
    }
    __syncwarp();

    // ---- xu1[i] = x_i.u1, xu2[i] = x_i.u2 (fp32) ----
    {
        int i14 = l & 15, h = l >> 4;
        const float* xr  = sx + i14 * 68 + h * 32;
        const float* u1p = su1 + h * 32;
        const float* u2p = su2 + h * 32;
        float a = 0.f, b = 0.f;
        #pragma unroll
        for (int c = 0; c < 32; c++) {
            float xv = xr[c];
            a = fmaf(xv, u1p[c], a);
            b = fmaf(xv, u2p[c], b);
        }
        a += __shfl_xor_sync(FULLMASK, a, 16);
        b += __shfl_xor_sync(FULLMASK, b, 16);
        if (h == 0) { sxu1[i14] = a; sxu2[i14] = b; }
    }
    __syncwarp();

    // ---- Y = x @ A  (M16 N64 K64: 64 MMAs) ----
    {
        float d[8][4] = {};
        #pragma unroll
        for (int k0 = 0; k0 < 8; k0++) {
            uint32_t a0 = fbits(sx[g * 68 + k0 * 8 + tg]);
            uint32_t a1 = fbits(sx[(g + 8) * 68 + k0 * 8 + tg]);
            uint32_t a2 = fbits(sx[g * 68 + k0 * 8 + tg + 4]);
            uint32_t a3 = fbits(sx[(g + 8) * 68 + k0 * 8 + tg + 4]);
            #pragma unroll
            for (int n0 = 0; n0 < 8; n0++) {
                uint32_t b0 = fbits(sA[(k0 * 8 + tg) * 72 + n0 * 8 + g]);
                uint32_t b1 = fbits(sA[(k0 * 8 + tg + 4) * 72 + n0 * 8 + g]);
                mma8(d[n0], a0, a1, a2, a3, b0, b1);
            }
        }
        #pragma unroll
        for (int n0 = 0; n0 < 8; n0++) {
            *(float2*)(sy + g * 68 + n0 * 8 + 2 * tg) =
                make_float2(tf32f(d[n0][0]), tf32f(d[n0][1]));
            *(float2*)(sy + (g + 8) * 68 + n0 * 8 + 2 * tg) =
                make_float2(tf32f(d[n0][2]), tf32f(d[n0][3]));
        }
    }
    __syncwarp();

    // ---- energy = y @ x^T + biases  (M16 N16 K64: 16 MMAs) ----
    {
        float e[2][4] = {};
        #pragma unroll
        for (int k0 = 0; k0 < 8; k0++) {
            uint32_t a0 = fbits(sy[g * 68 + k0 * 8 + tg]);
            uint32_t a1 = fbits(sy[(g + 8) * 68 + k0 * 8 + tg]);
            uint32_t a2 = fbits(sy[g * 68 + k0 * 8 + tg + 4]);
            uint32_t a3 = fbits(sy[(g + 8) * 68 + k0 * 8 + tg + 4]);
            #pragma unroll
            for (int nt = 0; nt < 2; nt++) {
                uint32_t b0 = fbits(sx[(nt * 8 + g) * 68 + k0 * 8 + tg]);
                uint32_t b1 = fbits(sx[(nt * 8 + g) * 68 + k0 * 8 + tg + 4]);
                mma8(e[nt], a0, a1, a2, a3, b0, b1);
            }
        }
        __syncwarp();   // all lanes done reading y before overwrite
        float xg0 = sxu1[g] + c0, xg8 = sxu1[g + 8] + c0;
        #pragma unroll
        for (int nt = 0; nt < 2; nt++) {
            int j0 = nt * 8 + 2 * tg;
            float u0 = sxu2[j0], u1v = sxu2[j0 + 1];
            *(float2*)(sy + g * 24 + j0) =
                make_float2(tf32f(e[nt][0] + xg0 + u0), tf32f(e[nt][1] + xg0 + u1v));
            *(float2*)(sy + (g + 8) * 24 + j0) =
                make_float2(tf32f(e[nt][2] + xg8 + u0), tf32f(e[nt][3] + xg8 + u1v));
        }
    }
    __syncwarp();

    // ---- mix = w_c @ energy (4 MMAs), then LN + softmax in regs ----
    float att0[2], att1[2], att2[2], att3[2];
    {
        float m[2][4] = {};
        #pragma unroll
        for (int k0 = 0; k0 < 2; k0++) {
            uint32_t a0 = fbits(swc[g * 20 + k0 * 8 + tg]);
            uint32_t a1 = fbits(swc[(g + 8) * 20 + k0 * 8 + tg]);
            uint32_t a2 = fbits(swc[g * 20 + k0 * 8 + tg + 4]);
            uint32_t a3 = fbits(swc[(g + 8) * 20 + k0 * 8 + tg + 4]);
            #pragma unroll
            for (int nt = 0; nt < 2; nt++) {
                uint32_t b0 = fbits(sy[(k0 * 8 + tg) * 24 + nt * 8 + g]);
                uint32_t b1 = fbits(sy[(k0 * 8 + tg + 4) * 24 + nt * 8 + g]);
                mma8(m[nt], a0, a1, a2, a3, b0, b1);
            }
        }
        const bool m3 = (tg == 3);   // this lane's v=14,15 slots (nt=1 pair)
        float lg0 = slg[2 * tg], lg1 = slg[2 * tg + 1];
        float lg2 = slg[8 + 2 * tg], lg3 = slg[9 + 2 * tg];
        float lb0 = slb[2 * tg], lb1 = slb[2 * tg + 1];
        float lb2 = slb[8 + 2 * tg], lb3 = slb[9 + 2 * tg];
        #pragma unroll
        for (int rr = 0; rr < 2; rr++) {
            float v0 = m[0][2 * rr], v1 = m[0][2 * rr + 1];
            float v2 = m[1][2 * rr], v3 = m[1][2 * rr + 1];
            float s = v0 + v1 + (m3 ? 0.f : (v2 + v3));
            s += __shfl_xor_sync(FULLMASK, s, 1);
            s += __shfl_xor_sync(FULLMASK, s, 2);
            float mu = s * (1.f / 14.f);
            float d0 = v0 - mu, d1 = v1 - mu, d2 = v2 - mu, d3 = v3 - mu;
            float q = d0 * d0 + d1 * d1 + (m3 ? 0.f : (d2 * d2 + d3 * d3));
            q += __shfl_xor_sync(FULLMASK, q, 1);
            q += __shfl_xor_sync(FULLMASK, q, 2);
            float rsv = rsqrtf(q * (1.f / 14.f) + 1e-5f);
            float t0 = (d0 * rsv * lg0 + lb0) * 0.125f;
            float t1 = (d1 * rsv * lg1 + lb1) * 0.125f;
            float t2 = (d2 * rsv * lg2 + lb2) * 0.125f;
            float t3 = (d3 * rsv * lg3 + lb3) * 0.125f;
            float mx = fmaxf(fmaxf(t0, t1), m3 ? -1e30f : fmaxf(t2, t3));
            mx = fmaxf(mx, __shfl_xor_sync(FULLMASK, mx, 1));
            mx = fmaxf(mx, __shfl_xor_sync(FULLMASK, mx, 2));
            float e0 = __expf(t0 - mx), e1 = __expf(t1 - mx);
            float e2 = m3 ? 0.f : __expf(t2 - mx);
            float e3 = m3 ? 0.f : __expf(t3 - mx);
            float ss = e0 + e1 + e2 + e3;
            ss += __shfl_xor_sync(FULLMASK, ss, 1);
            ss += __shfl_xor_sync(FULLMASK, ss, 2);
            float inv = 1.f / ss;
            att0[rr] = e0 * inv; att1[rr] = e1 * inv;
            att2[rr] = e2 * inv; att3[rr] = e3 * inv;
        }
    }
    __syncwarp();   // mix reads of energy done before att overwrite
    *(float2*)(sy + g * 24 + 2 * tg)           = make_float2(tf32f(att0[0]), tf32f(att1[0]));
    *(float2*)(sy + g * 24 + 8 + 2 * tg)       = make_float2(tf32f(att2[0]), tf32f(att3[0]));
    *(float2*)(sy + (g + 8) * 24 + 2 * tg)     = make_float2(tf32f(att0[1]), tf32f(att1[1]));
    *(float2*)(sy + (g + 8) * 24 + 8 + 2 * tg) = make_float2(tf32f(att2[1]), tf32f(att3[1]));
    __syncwarp();

    // ---- z = att @ x  (M16 N64 K16: 16 MMAs) ----
    {
        float zd[8][4] = {};
        #pragma unroll
        for (int k0 = 0; k0 < 2; k0++) {
            uint32_t a0 = fbits(sy[g * 24 + k0 * 8 + tg]);
            uint32_t a1 = fbits(sy[(g + 8) * 24 + k0 * 8 + tg]);
            uint32_t a2 = fbits(sy[g * 24 + k0 * 8 + tg + 4]);
            uint32_t a3 = fbits(sy[(g + 8) * 24 + k0 * 8 + tg + 4]);
            #pragma unroll
            for (int n0 = 0; n0 < 8; n0++) {
                uint32_t b0 = fbits(sx[(k0 * 8 + tg) * 68 + n0 * 8 + g]);
                uint32_t b1 = fbits(sx[(k0 * 8 + tg + 4) * 68 + n0 * 8 + g]);
                mma8(zd[n0], a0, a1, a2, a3, b0, b1);
            }
        }
        __syncwarp();   // att reads done before z overwrite
        #pragma unroll
        for (int n0 = 0; n0 < 8; n0++) {
            *(float2*)(sy + g * 68 + n0 * 8 + 2 * tg) =
                make_float2(tf32f(zd[n0][0]), tf32f(zd[n0][1]));
            *(float2*)(sy + (g + 8) * 68 + n0 * 8 + 2 * tg) =
                make_float2(tf32f(zd[n0][2]), tf32f(zd[n0][3]));
        }
    }
    __syncwarp();

    // ---- out = z @ Wv^T + bv  (64 MMAs) ----
    {
        float od[8][4] = {};
        #pragma unroll
        for (int k0 = 0; k0 < 8; k0++) {
            uint32_t a0 = fbits(sy[g * 68 + k0 * 8 + tg]);
            uint32_t a1 = fbits(sy[(g + 8) * 68 + k0 * 8 + tg]);
            uint32_t a2 = fbits(sy[g * 68 + k0 * 8 + tg + 4]);
            uint32_t a3 = fbits(sy[(g + 8) * 68 + k0 * 8 + tg + 4]);
            #pragma unroll
            for (int n0 = 0; n0 < 8; n0++) {
                uint32_t b0 = fbits(sW[(k0 * 8 + tg) * 72 + n0 * 8 + g]);
                uint32_t b1 = fbits(sW[(k0 * 8 + tg + 4) * 72 + n0 * 8 + g]);
                mma8(od[n0], a0, a1, a2, a3, b0, b1);
            }
        }
        float* og = out + pair * 896;
        #pragma unroll
        for (int n0 = 0; n0 < 8; n0++) {
            int cc = n0 * 8 + 2 * tg;
            float2 bb = *(const float2*)(sbv + cc);
            *(float2*)(og + g * 64 + cc) =
                make_float2(od[n0][0] + bb.x, od[n0][1] + bb.y);
            if (g < 6)
                *(float2*)(og + (g + 8) * 64 + cc) =
                    make_float2(od[n0][2] + bb.x, od[n0][3] + bb.y);
        }
    }
}

// ---------------------------------------------------------------------------
extern "C" void kernel_launch(void* const* d_in, const int* in_sizes, int n_in,
                              void* d_out, int out_size) {
    const float* x   = (const float*)d_in[0];
    const float* wc  = (const float*)d_in[1];
    const float* Wq  = (const float*)d_in[2];
    const float* bq  = (const float*)d_in[3];
    const float* Wk  = (const float*)d_in[4];
    const float* bk  = (const float*)d_in[5];
    const float* Wv  = (const float*)d_in[6];
    const float* bv  = (const float*)d_in[7];
    const float* lng = (const float*)d_in[8];
    const float* lnb = (const float*)d_in[9];
    float* out = (float*)d_out;

    cudaFuncSetAttribute(attn_kernel, cudaFuncAttributeMaxDynamicSharedMemorySize,
                         SMEM_FLOATS * 4);

    prep_kernel<<<1, 256>>>(Wq, bq, Wk, bk, Wv, wc);
    attn_kernel<<<8192, 256, SMEM_FLOATS * 4>>>(x, bv, lng, lnb, out);
}

// round 5
// speedup vs baseline: 1.8162x; 1.1536x over previous
#include <cuda_runtime.h>
#include <cstdint>

// ---------------------------------------------------------------------------
// ChannelMultiHeadAttention, fp32 in/out, tf32 tensor-core compute.
//   energy = x A x^T + xu1 1^T + 1 xu2^T + c0,  A = Wq^T Wk
//   out    = (att @ x) Wv^T + bv
// R5: shuffle-based fragment relayout (no y/att smem round-trips),
//     10 warps/CTA -> 20 warps/SM.
// ---------------------------------------------------------------------------

#define FULLMASK 0xffffffffu

__device__ float g_A[4096];    // A[d][e] = (Wq^T Wk)[d][e], tf32-rounded
__device__ float g_W[4096];    // W[d][e] = Wv[e][d], tf32-rounded
__device__ float g_wc[256];    // w_c padded 16x16, tf32-rounded (pad = 0)
__device__ float g_u1[64], g_u2[64], g_c0[1];

__device__ __forceinline__ uint32_t tf32r(float f) {
    uint32_t u; asm("cvt.rna.tf32.f32 %0, %1;" : "=r"(u) : "f"(f)); return u;
}
__device__ __forceinline__ float tf32f(float f) { return __uint_as_float(tf32r(f)); }
__device__ __forceinline__ uint32_t fbits(float f) { return __float_as_uint(f); }

__device__ __forceinline__ void mma8(float* d, uint32_t a0, uint32_t a1, uint32_t a2,
                                     uint32_t a3, uint32_t b0, uint32_t b1) {
    asm("mma.sync.aligned.m16n8k8.row.col.f32.tf32.tf32.f32 "
        "{%0,%1,%2,%3}, {%4,%5,%6,%7}, {%8,%9}, {%0,%1,%2,%3};"
        : "+f"(d[0]), "+f"(d[1]), "+f"(d[2]), "+f"(d[3])
        : "r"(a0), "r"(a1), "r"(a2), "r"(a3), "r"(b0), "r"(b1));
}

// ---------------------------------------------------------------------------
__global__ void prep_kernel(const float* __restrict__ Wq, const float* __restrict__ bq,
                            const float* __restrict__ Wk, const float* __restrict__ bk,
                            const float* __restrict__ Wv, const float* __restrict__ wc) {
    __shared__ float sWq[4096], sWk[4096];
    int t = threadIdx.x;
    for (int i = t; i < 4096; i += 256) { sWq[i] = Wq[i]; sWk[i] = Wk[i]; }
    __syncthreads();
    for (int idx = t; idx < 4096; idx += 256) {
        int d = idx >> 6, e = idx & 63;
        float a = 0.f;
        #pragma unroll 8
        for (int f = 0; f < 64; f++) a += sWq[f * 64 + d] * sWk[f * 64 + e];
        g_A[idx] = tf32f(a);
        g_W[idx] = tf32f(Wv[e * 64 + d]);   // W[d][e] = Wv[e][d]
    }
    if (t < 256) {
        int a = t >> 4, c = t & 15;
        float v = (a < 14 && c < 14) ? wc[a * 14 + c] : 0.f;
        g_wc[t] = tf32f(v);
    }
    if (t < 64) {
        float s1 = 0.f, s2 = 0.f;
        for (int f = 0; f < 64; f++) {
            s1 += sWq[f * 64 + t] * bk[f];
            s2 += sWk[f * 64 + t] * bq[f];
        }
        g_u1[t] = s1; g_u2[t] = s2;
    }
    if (t == 0) {
        float c = 0.f;
        for (int f = 0; f < 64; f++) c += bq[f] * bk[f];
        g_c0[0] = c;
    }
}

// ---------------------------------------------------------------------------
// Main: 1 warp = 1 pair, 10 warps/CTA, 6554 CTAs (tail-guarded).
// Per-warp smem: x tile 16x68 + 32 (xu).  Shared: sA/sW stride 72, w_c stride 20.
// ---------------------------------------------------------------------------
static const int NW = 10;
static const int SMEM_FLOATS = 9760 + NW * 1120;   // 20960 -> 83840 B
static const int NPAIRS = 65536;

__global__ __launch_bounds__(32 * NW, 2)
void attn_kernel(const float* __restrict__ x, const float* __restrict__ bv,
                 const float* __restrict__ lng, const float* __restrict__ lnb,
                 float* __restrict__ out) {
    extern __shared__ float sf[];
    float* sA  = sf;            // 64 x 72
    float* sW  = sf + 4608;     // 64 x 72
    float* swc = sf + 9216;     // 16 x 20
    float* su1 = sf + 9536;
    float* su2 = sf + 9600;
    float* sbv = sf + 9664;
    float* slg = sf + 9728;
    float* slb = sf + 9744;     // per-warp tiles start at 9760

    const int t = threadIdx.x, w = t >> 5, l = t & 31;
    const int g = l >> 2, tg = l & 3;

    for (int i = t; i < 4096; i += 32 * NW) {
        int d = i >> 6, e = i & 63;
        sA[d * 72 + e] = g_A[i];
        sW[d * 72 + e] = g_W[i];
    }
    if (t < 256) { int a = t >> 4, c = t & 15; swc[a * 20 + c] = g_wc[t]; }
    if (t < 64) { su1[t] = g_u1[t]; su2[t] = g_u2[t]; sbv[t] = bv[t]; }
    if (t < 16) {
        slg[t] = (t < 14) ? lng[t] : 0.f;
        slb[t] = (t < 14) ? lnb[t] : 0.f;
    }
    __syncthreads();

    const size_t pair = (size_t)blockIdx.x * NW + w;
    if (pair >= NPAIRS) return;
    const float c0 = g_c0[0];

    float* sx   = sf + 9760 + w * 1120;   // 16 x 68
    float* sxu1 = sx + 1088;              // 16
    float* sxu2 = sx + 1104;              // 16

    // ---- load x tile, round to tf32, zero pad rows 14/15 ----
    const float4* xg4 = (const float4*)(x + pair * 896);
    #pragma unroll
    for (int it = 0; it < 7; it++) {
        int k = l + 32 * it;
        float4 v = xg4[k];
        int row = k >> 4, c = (k & 15) << 2;
        *(float4*)(sx + row * 68 + c) =
            make_float4(tf32f(v.x), tf32f(v.y), tf32f(v.z), tf32f(v.w));
    }
    if (l < 16) {
        float4 z4 = make_float4(0.f, 0.f, 0.f, 0.f);
        *(float4*)(sx + 14 * 68 + 4 * l) = z4;
        *(float4*)(sx + 15 * 68 + 4 * l) = z4;
    }
    __syncwarp();

    // ---- xu1[i] = x_i.u1, xu2[i] = x_i.u2 (fp32) ----
    {
        int i14 = l & 15, h = l >> 4;
        const float* xr  = sx + i14 * 68 + h * 32;
        const float* u1p = su1 + h * 32;
        const float* u2p = su2 + h * 32;
        float a = 0.f, b = 0.f;
        #pragma unroll
        for (int c = 0; c < 32; c++) {
            float xv = xr[c];
            a = fmaf(xv, u1p[c], a);
            b = fmaf(xv, u2p[c], b);
        }
        a += __shfl_xor_sync(FULLMASK, a, 16);
        b += __shfl_xor_sync(FULLMASK, b, 16);
        if (h == 0) { sxu1[i14] = a; sxu2[i14] = b; }
    }
    __syncwarp();

    const int srcA = 4 * g + (tg >> 1);   // quad-local relayout sources
    const int srcB = srcA + 2;
    const bool pr = tg & 1;

    // ---- Y = x @ A  (M16 N64 K64: 64 MMAs), results stay in regs ----
    float dY[8][4] = {};
    #pragma unroll
    for (int k0 = 0; k0 < 8; k0++) {
        uint32_t a0 = fbits(sx[g * 68 + k0 * 8 + tg]);
        uint32_t a1 = fbits(sx[(g + 8) * 68 + k0 * 8 + tg]);
        uint32_t a2 = fbits(sx[g * 68 + k0 * 8 + tg + 4]);
        uint32_t a3 = fbits(sx[(g + 8) * 68 + k0 * 8 + tg + 4]);
        #pragma unroll
        for (int n0 = 0; n0 < 8; n0++) {
            uint32_t b0 = fbits(sA[(k0 * 8 + tg) * 72 + n0 * 8 + g]);
            uint32_t b1 = fbits(sA[(k0 * 8 + tg + 4) * 72 + n0 * 8 + g]);
            mma8(dY[n0], a0, a1, a2, a3, b0, b1);
        }
    }
    // pre-round y to tf32 (same rounding point as R4's smem store)
    #pragma unroll
    for (int n0 = 0; n0 < 8; n0++)
        #pragma unroll
        for (int j = 0; j < 4; j++) dY[n0][j] = tf32f(dY[n0][j]);

    // ---- energy = y @ x^T + biases  (16 MMAs); y A-frags via shuffle ----
    float et[2][4];
    {
        float e[2][4] = {};
        #pragma unroll
        for (int k0 = 0; k0 < 8; k0++) {
            float v0 = __shfl_sync(FULLMASK, dY[k0][0], srcA);
            float v1 = __shfl_sync(FULLMASK, dY[k0][1], srcA);
            float v2 = __shfl_sync(FULLMASK, dY[k0][2], srcA);
            float v3 = __shfl_sync(FULLMASK, dY[k0][3], srcA);
            float w0 = __shfl_sync(FULLMASK, dY[k0][0], srcB);
            float w1 = __shfl_sync(FULLMASK, dY[k0][1], srcB);
            float w2 = __shfl_sync(FULLMASK, dY[k0][2], srcB);
            float w3 = __shfl_sync(FULLMASK, dY[k0][3], srcB);
            uint32_t a0 = fbits(pr ? v1 : v0);
            uint32_t a1 = fbits(pr ? v3 : v2);
            uint32_t a2 = fbits(pr ? w1 : w0);
            uint32_t a3 = fbits(pr ? w3 : w2);
            #pragma unroll
            for (int nt = 0; nt < 2; nt++) {
                uint32_t b0 = fbits(sx[(nt * 8 + g) * 68 + k0 * 8 + tg]);
                uint32_t b1 = fbits(sx[(nt * 8 + g) * 68 + k0 * 8 + tg + 4]);
                mma8(e[nt], a0, a1, a2, a3, b0, b1);
            }
        }
        float xg0 = sxu1[g] + c0, xg8 = sxu1[g + 8] + c0;
        #pragma unroll
        for (int nt = 0; nt < 2; nt++) {
            int j0 = nt * 8 + 2 * tg;
            float u0 = sxu2[j0], u1v = sxu2[j0 + 1];
            et[nt][0] = tf32f(e[nt][0] + xg0 + u0);
            et[nt][1] = tf32f(e[nt][1] + xg0 + u1v);
            et[nt][2] = tf32f(e[nt][2] + xg8 + u0);
            et[nt][3] = tf32f(e[nt][3] + xg8 + u1v);
        }
    }

    // ---- mix = w_c @ energy (4 MMAs); energy B-frags via shuffle ----
    float att0[2], att1[2], att2[2], att3[2];
    {
        const int srcM  = 4 * tg + (g >> 1);       // row 8k0+tg source
        const int srcM4 = 16 + 4 * tg + (g >> 1);  // row 8k0+tg+4 source
        const bool pg = g & 1;
        float m[2][4] = {};
        #pragma unroll
        for (int k0 = 0; k0 < 2; k0++) {
            uint32_t a0 = fbits(swc[g * 20 + k0 * 8 + tg]);
            uint32_t a1 = fbits(swc[(g + 8) * 20 + k0 * 8 + tg]);
            uint32_t a2 = fbits(swc[g * 20 + k0 * 8 + tg + 4]);
            uint32_t a3 = fbits(swc[(g + 8) * 20 + k0 * 8 + tg + 4]);
            #pragma unroll
            for (int nt = 0; nt < 2; nt++) {
                float v0 = __shfl_sync(FULLMASK, et[nt][2 * k0], srcM);
                float v1 = __shfl_sync(FULLMASK, et[nt][2 * k0 + 1], srcM);
                float w0 = __shfl_sync(FULLMASK, et[nt][2 * k0], srcM4);
                float w1 = __shfl_sync(FULLMASK, et[nt][2 * k0 + 1], srcM4);
                uint32_t b0 = fbits(pg ? v1 : v0);
                uint32_t b1 = fbits(pg ? w1 : w0);
                mma8(m[nt], a0, a1, a2, a3, b0, b1);
            }
        }
        // ---- LayerNorm + softmax in regs (quad reductions) ----
        const bool m3 = (tg == 3);   // cols 14,15
        float lg0 = slg[2 * tg], lg1 = slg[2 * tg + 1];
        float lg2 = slg[8 + 2 * tg], lg3 = slg[9 + 2 * tg];
        float lb0 = slb[2 * tg], lb1 = slb[2 * tg + 1];
        float lb2 = slb[8 + 2 * tg], lb3 = slb[9 + 2 * tg];
        #pragma unroll
        for (int rr = 0; rr < 2; rr++) {
            float v0 = m[0][2 * rr], v1 = m[0][2 * rr + 1];
            float v2 = m[1][2 * rr], v3 = m[1][2 * rr + 1];
            float s = v0 + v1 + (m3 ? 0.f : (v2 + v3));
            s += __shfl_xor_sync(FULLMASK, s, 1);
            s += __shfl_xor_sync(FULLMASK, s, 2);
            float mu = s * (1.f / 14.f);
            float d0 = v0 - mu, d1 = v1 - mu, d2 = v2 - mu, d3 = v3 - mu;
            float q = d0 * d0 + d1 * d1 + (m3 ? 0.f : (d2 * d2 + d3 * d3));
            q += __shfl_xor_sync(FULLMASK, q, 1);
            q += __shfl_xor_sync(FULLMASK, q, 2);
            float rsv = rsqrtf(q * (1.f / 14.f) + 1e-5f);
            float t0 = (d0 * rsv * lg0 + lb0) * 0.125f;
            float t1 = (d1 * rsv * lg1 + lb1) * 0.125f;
            float t2 = (d2 * rsv * lg2 + lb2) * 0.125f;
            float t3 = (d3 * rsv * lg3 + lb3) * 0.125f;
            float mx = fmaxf(fmaxf(t0, t1), m3 ? -1e30f : fmaxf(t2, t3));
            mx = fmaxf(mx, __shfl_xor_sync(FULLMASK, mx, 1));
            mx = fmaxf(mx, __shfl_xor_sync(FULLMASK, mx, 2));
            float e0 = __expf(t0 - mx), e1 = __expf(t1 - mx);
            float e2 = m3 ? 0.f : __expf(t2 - mx);
            float e3 = m3 ? 0.f : __expf(t3 - mx);
            float ss = e0 + e1 + e2 + e3;
            ss += __shfl_xor_sync(FULLMASK, ss, 1);
            ss += __shfl_xor_sync(FULLMASK, ss, 2);
            float inv = 1.f / ss;
            att0[rr] = tf32f(e0 * inv); att1[rr] = tf32f(e1 * inv);
            att2[rr] = tf32f(e2 * inv); att3[rr] = tf32f(e3 * inv);
        }
    }

    // ---- z = att @ x  (16 MMAs); att A-frags via shuffle ----
    float zd[8][4] = {};
    #pragma unroll
    for (int k0 = 0; k0 < 2; k0++) {
        float p0, p1, q0, q1, p2, p3, q2, q3;
        if (k0 == 0) {
            p0 = __shfl_sync(FULLMASK, att0[0], srcA);
            p1 = __shfl_sync(FULLMASK, att1[0], srcA);
            p2 = __shfl_sync(FULLMASK, att0[1], srcA);
            p3 = __shfl_sync(FULLMASK, att1[1], srcA);
            q0 = __shfl_sync(FULLMASK, att0[0], srcB);
            q1 = __shfl_sync(FULLMASK, att1[0], srcB);
            q2 = __shfl_sync(FULLMASK, att0[1], srcB);
            q3 = __shfl_sync(FULLMASK, att1[1], srcB);
        } else {
            p0 = __shfl_sync(FULLMASK, att2[0], srcA);
            p1 = __shfl_sync(FULLMASK, att3[0], srcA);
            p2 = __shfl_sync(FULLMASK, att2[1], srcA);
            p3 = __shfl_sync(FULLMASK, att3[1], srcA);
            q0 = __shfl_sync(FULLMASK, att2[0], srcB);
            q1 = __shfl_sync(FULLMASK, att3[0], srcB);
            q2 = __shfl_sync(FULLMASK, att2[1], srcB);
            q3 = __shfl_sync(FULLMASK, att3[1], srcB);
        }
        uint32_t a0 = fbits(pr ? p1 : p0);
        uint32_t a1 = fbits(pr ? p3 : p2);
        uint32_t a2 = fbits(pr ? q1 : q0);
        uint32_t a3 = fbits(pr ? q3 : q2);
        #pragma unroll
        for (int n0 = 0; n0 < 8; n0++) {
            uint32_t b0 = fbits(sx[(k0 * 8 + tg) * 68 + n0 * 8 + g]);
            uint32_t b1 = fbits(sx[(k0 * 8 + tg + 4) * 68 + n0 * 8 + g]);
            mma8(zd[n0], a0, a1, a2, a3, b0, b1);
        }
    }
    __syncwarp();   // all x reads done; reuse sx for z
    #pragma unroll
    for (int n0 = 0; n0 < 8; n0++) {
        *(float2*)(sx + g * 68 + n0 * 8 + 2 * tg) =
            make_float2(tf32f(zd[n0][0]), tf32f(zd[n0][1]));
        *(float2*)(sx + (g + 8) * 68 + n0 * 8 + 2 * tg) =
            make_float2(tf32f(zd[n0][2]), tf32f(zd[n0][3]));
    }
    __syncwarp();

    // ---- out = z @ Wv^T + bv  (64 MMAs) ----
    {
        float od[8][4] = {};
        #pragma unroll
        for (int k0 = 0; k0 < 8; k0++) {
            uint32_t a0 = fbits(sx[g * 68 + k0 * 8 + tg]);
            uint32_t a1 = fbits(sx[(g + 8) * 68 + k0 * 8 + tg]);
            uint32_t a2 = fbits(sx[g * 68 + k0 * 8 + tg + 4]);
            uint32_t a3 = fbits(sx[(g + 8) * 68 + k0 * 8 + tg + 4]);
            #pragma unroll
            for (int n0 = 0; n0 < 8; n0++) {
                uint32_t b0 = fbits(sW[(k0 * 8 + tg) * 72 + n0 * 8 + g]);
                uint32_t b1 = fbits(sW[(k0 * 8 + tg + 4) * 72 + n0 * 8 + g]);
                mma8(od[n0], a0, a1, a2, a3, b0, b1);
            }
        }
        float* og = out + pair * 896;
        #pragma unroll
        for (int n0 = 0; n0 < 8; n0++) {
            int cc = n0 * 8 + 2 * tg;
            float2 bb = *(const float2*)(sbv + cc);
            *(float2*)(og + g * 64 + cc) =
                make_float2(od[n0][0] + bb.x, od[n0][1] + bb.y);
            if (g < 6)
                *(float2*)(og + (g + 8) * 64 + cc) =
                    make_float2(od[n0][2] + bb.x, od[n0][3] + bb.y);
        }
    }
}

// ---------------------------------------------------------------------------
extern "C" void kernel_launch(void* const* d_in, const int* in_sizes, int n_in,
                              void* d_out, int out_size) {
    const float* x   = (const float*)d_in[0];
    const float* wc  = (const float*)d_in[1];
    const float* Wq  = (const float*)d_in[2];
    const float* bq  = (const float*)d_in[3];
    const float* Wk  = (const float*)d_in[4];
    const float* bk  = (const float*)d_in[5];
    const float* Wv  = (const float*)d_in[6];
    const float* bv  = (const float*)d_in[7];
    const float* lng = (const float*)d_in[8];
    const float* lnb = (const float*)d_in[9];
    float* out = (float*)d_out;

    cudaFuncSetAttribute(attn_kernel, cudaFuncAttributeMaxDynamicSharedMemorySize,
                         SMEM_FLOATS * 4);

    prep_kernel<<<1, 256>>>(Wq, bq, Wk, bk, Wv, wc);
    int nblk = (NPAIRS + NW - 1) / NW;
    attn_kernel<<<nblk, 32 * NW, SMEM_FLOATS * 4>>>(x, bv, lng, lnb, out);
}